// round 9
// baseline (speedup 1.0000x reference)
#include <cuda_runtime.h>
#include <math.h>

#define BB 1024
#define SS 64
#define DD 256
#define CHN 1024
#define NCH 8    // samples per chunk (k_hidden)

typedef unsigned long long u64;

// scratch (device globals; no allocation allowed)
__device__ int   g_idx[BB];
__device__ int   g_cnt[SS];               // per-scene sample counts
__device__ int   g_list[SS][BB];          // per-scene sample lists (global ordering)
__device__ __align__(16) float g_desc[2][BB][DD];   // gathered descriptors (t, rot)

// ---- packed f32x2 helpers (Blackwell) --------------------------------------
__device__ __forceinline__ u64 dup2(float w) {
    unsigned u = __float_as_uint(w);
    u64 r; asm("mov.b64 %0, {%1, %2};" : "=l"(r) : "r"(u), "r"(u)); return r;
}
__device__ __forceinline__ float2 unpk2(u64 v) {
    unsigned lo, hi; asm("mov.b64 {%0, %1}, %2;" : "=r"(lo), "=r"(hi) : "l"(v));
    return make_float2(__uint_as_float(lo), __uint_as_float(hi));
}
__device__ __forceinline__ u64 ffma2(u64 a, u64 b, u64 c) {
    u64 d; asm("fma.rn.f32x2 %0, %1, %2, %3;" : "=l"(d) : "l"(a), "l"(b), "l"(c));
    return d;
}

// ---------------------------------------------------------------------------
// K1: logits for 4 rows per warp (16 LDG.128 in flight, W regs shared x4).
// Block 0 also zeroes g_cnt (safe: consumers are in later kernels).
// ---------------------------------------------------------------------------
__global__ void __launch_bounds__(256) k_logits(
        const float* __restrict__ t, const float* __restrict__ r,
        const float* __restrict__ Wsc, const float* __restrict__ bsc,
        float* __restrict__ logits) {
    if (blockIdx.x == 0 && threadIdx.x < SS) g_cnt[threadIdx.x] = 0;
    int g    = blockIdx.x * 8 + (threadIdx.x >> 5);   // warp id
    int lane = threadIdx.x & 31;
    int w0   = g * 4;
    if (w0 >= BB * SS) return;
    const float4* t4 = (const float4*)(t + (size_t)w0 * DD);
    const float4* r4 = (const float4*)(r + (size_t)w0 * DD);
    const float4* W4 = (const float4*)Wsc;
    float acc[4] = {0.f, 0.f, 0.f, 0.f};
#pragma unroll
    for (int j = 0; j < 2; j++) {
        int k = j * 32 + lane;
        float4 wa = W4[k];
        float4 wb = W4[64 + k];
#pragma unroll
        for (int i = 0; i < 4; i++) {
            float4 a0 = t4[i * 64 + k];
            float4 b0 = r4[i * 64 + k];
            acc[i] = fmaf(a0.x, wa.x, acc[i]); acc[i] = fmaf(a0.y, wa.y, acc[i]);
            acc[i] = fmaf(a0.z, wa.z, acc[i]); acc[i] = fmaf(a0.w, wa.w, acc[i]);
            acc[i] = fmaf(b0.x, wb.x, acc[i]); acc[i] = fmaf(b0.y, wb.y, acc[i]);
            acc[i] = fmaf(b0.z, wb.z, acc[i]); acc[i] = fmaf(b0.w, wb.w, acc[i]);
        }
    }
#pragma unroll
    for (int o = 16; o; o >>= 1) {
#pragma unroll
        for (int i = 0; i < 4; i++)
            acc[i] += __shfl_xor_sync(0xFFFFFFFFu, acc[i], o);
    }
    if (lane == 0) {
        float bb = bsc[0];
#pragma unroll
        for (int i = 0; i < 4; i++) logits[w0 + i] = acc[i] + bb;
    }
}

// ---------------------------------------------------------------------------
// K2: log_softmax + argmax (warp-parallel) + scene-list append + gather + bias
// ---------------------------------------------------------------------------
__global__ void k_softmax_gather(const float* __restrict__ t, const float* __restrict__ r,
                                 const float* __restrict__ bto, const float* __restrict__ bro,
                                 float* __restrict__ logd, float* __restrict__ pose) {
    int b    = blockIdx.x;
    int tid  = threadIdx.x;
    int wid  = tid >> 5;
    int lane = tid & 31;
    __shared__ float l[SS];
    __shared__ float lse;
    __shared__ int   am;
    if (tid < SS) l[tid] = logd[b * SS + tid];
    __syncthreads();
    if (wid == 0) {
        float v0 = l[lane], v1 = l[lane + 32];
        float m; int a;
        if (v1 > v0) { m = v1; a = lane + 32; } else { m = v0; a = lane; }
#pragma unroll
        for (int o = 16; o; o >>= 1) {
            float mo = __shfl_down_sync(0xFFFFFFFFu, m, o);
            int   ao = __shfl_down_sync(0xFFFFFFFFu, a, o);
            if (mo > m || (mo == m && ao < a)) { m = mo; a = ao; }
        }
        m = __shfl_sync(0xFFFFFFFFu, m, 0);
        a = __shfl_sync(0xFFFFFFFFu, a, 0);
        float s = expf(v0 - m) + expf(v1 - m);
#pragma unroll
        for (int o = 16; o; o >>= 1) s += __shfl_xor_sync(0xFFFFFFFFu, s, o);
        if (lane == 0) {
            lse = m + logf(s);
            am  = a;
            g_idx[b] = a;
            int p = atomicAdd(&g_cnt[a], 1);   // single global ordering
            g_list[a][p] = b;
        }
    }
    __syncthreads();
    if (tid < SS) logd[b * SS + tid] = l[tid] - lse;
    int a = am;
    if (tid >= 224) {                          // pose bias init
        int o = tid - 224;
        if (o < 3)      pose[b * 7 + o] = bto[a * 3 + o];
        else if (o < 7) pose[b * 7 + o] = bro[a * 4 + (o - 3)];
    }
    if (tid < 64) {
        ((float4*)g_desc[0][b])[tid] =
            ((const float4*)(t + ((size_t)b * SS + a) * DD))[tid];
    } else if (tid < 128) {
        int i = tid - 64;
        ((float4*)g_desc[1][b])[i] =
            ((const float4*)(r + ((size_t)b * SS + a) * DD))[i];
    }
}

// ---------------------------------------------------------------------------
// K3: fused expert hidden layer + gelu + output projection (R6-proven shape).
// grid = (64 scenes, 2 heads, 4 jc chunk-slots), 256 threads.
// Thread owns 4 CONSECUTIVE channels (float4 weight LDG.128) x 8 samples
// (4 f32x2 pairs per channel) -> 16 u64 accumulators.
// ---------------------------------------------------------------------------
__global__ void __launch_bounds__(256, 3) k_hidden(
        const float* __restrict__ Wth, const float* __restrict__ bth,
        const float* __restrict__ Wto,
        const float* __restrict__ Wrh, const float* __restrict__ brh,
        const float* __restrict__ Wro,
        float* __restrict__ pose) {
    int scene = blockIdx.x;            // 0..63
    int head  = blockIdx.y;            // 0..1
    int jc    = blockIdx.z;            // chunk slot 0..3
    int tid   = threadIdx.x;
    int lane  = tid & 31;

    int cnt = g_cnt[scene];
    if (jc * NCH >= cnt) return;
    const int* list = g_list[scene];

    const float* W    = head ? Wrh : Wth;
    const float* bias = head ? brh : bth;
    const float* Wo   = head ? Wro : Wto;
    const int    NO   = head ? 4 : 3;
    const int    ooff = head ? 3 : 0;

    __shared__ __align__(16) float gs[DD][NCH + 2];   // transposed, padded
    __shared__ float part[NCH][4];

    int ch = tid * 4;                                  // 4 consecutive channels
    const float* Ws = W + (size_t)scene * DD * CHN;

    for (int c0 = jc * NCH; c0 < cnt; c0 += 4 * NCH) {
        int nc = min(NCH, cnt - c0);
        __syncthreads();    // protect gs/part reuse across chunks
        {
            const float* gd = &g_desc[head][0][0];
#pragma unroll
            for (int n = 0; n < NCH; n++) {
                float v = (n < nc) ? gd[(size_t)list[c0 + n] * DD + tid] : 0.f;
                gs[tid][n] = v;
            }
        }
        if (tid < NCH * 4) part[tid >> 2][tid & 3] = 0.f;
        __syncthreads();

        u64 acc[4][4];      // [channel][sample-pair]
#pragma unroll
        for (int c = 0; c < 4; c++)
#pragma unroll
            for (int p = 0; p < 4; p++) acc[c][p] = 0ull;

#pragma unroll 4
        for (int d = 0; d < DD; d++) {
            float4 wv = *(const float4*)&Ws[(size_t)d * CHN + ch];
            u64 wd[4] = {dup2(wv.x), dup2(wv.y), dup2(wv.z), dup2(wv.w)};
            const u64* grow = (const u64*)&gs[d][0];
#pragma unroll
            for (int p = 0; p < 4; p++) {
                u64 gp = grow[p];
#pragma unroll
                for (int c = 0; c < 4; c++)
                    acc[c][p] = ffma2(gp, wd[c], acc[c][p]);
            }
        }

        // epilogue (loads here to keep main-loop register pressure low)
        float4 bv = *(const float4*)&bias[(size_t)scene * CHN + ch];
        float bvs[4] = {bv.x, bv.y, bv.z, bv.w};
        float wo[4][4];
#pragma unroll
        for (int c = 0; c < 4; c++)
#pragma unroll
            for (int o = 0; o < 4; o++)
                wo[c][o] = (o < NO) ? Wo[((size_t)scene * CHN + ch + c) * NO + o] : 0.f;

#pragma unroll
        for (int p = 0; p < 4; p++) {
            float2 xs[4];
#pragma unroll
            for (int c = 0; c < 4; c++) xs[c] = unpk2(acc[c][p]);
#pragma unroll
            for (int q = 0; q < 2; q++) {
                int n = 2 * p + q;
                if (n < nc) {                       // warp-uniform
                    float pv[4] = {0.f, 0.f, 0.f, 0.f};
#pragma unroll
                    for (int c = 0; c < 4; c++) {
                        float x = (q ? xs[c].y : xs[c].x) + bvs[c];
                        float h = 0.5f * x * (1.0f + erff(x * 0.70710678118654752f));
#pragma unroll
                        for (int o = 0; o < 4; o++) pv[o] = fmaf(h, wo[c][o], pv[o]);
                    }
#pragma unroll
                    for (int off = 16; off; off >>= 1) {
                        pv[0] += __shfl_down_sync(0xFFFFFFFFu, pv[0], off);
                        pv[1] += __shfl_down_sync(0xFFFFFFFFu, pv[1], off);
                        pv[2] += __shfl_down_sync(0xFFFFFFFFu, pv[2], off);
                        pv[3] += __shfl_down_sync(0xFFFFFFFFu, pv[3], off);
                    }
                    if (lane == 0) {
                        atomicAdd(&part[n][0], pv[0]);
                        atomicAdd(&part[n][1], pv[1]);
                        atomicAdd(&part[n][2], pv[2]);
                        atomicAdd(&part[n][3], pv[3]);
                    }
                }
            }
        }
        __syncthreads();
        if (tid < NCH * 4) {
            int n = tid >> 2, o = tid & 3;
            if (n < nc && o < NO)
                atomicAdd(&pose[(size_t)list[c0 + n] * 7 + ooff + o], part[n][o]);
        }
    }
}

// ---------------------------------------------------------------------------
extern "C" void kernel_launch(void* const* d_in, const int* in_sizes, int n_in,
                              void* d_out, int out_size) {
    const float* t   = (const float*)d_in[0];
    const float* r   = (const float*)d_in[1];
    const float* Wsc = (const float*)d_in[2];
    const float* bsc = (const float*)d_in[3];
    const float* Wth = (const float*)d_in[4];
    const float* bth = (const float*)d_in[5];
    const float* Wto = (const float*)d_in[6];
    const float* bto = (const float*)d_in[7];
    const float* Wrh = (const float*)d_in[8];
    const float* brh = (const float*)d_in[9];
    const float* Wro = (const float*)d_in[10];
    const float* bro = (const float*)d_in[11];

    float* out  = (float*)d_out;
    float* pose = out;             // [B,7]
    float* logd = out + BB * 7;    // [B,S]

    k_logits<<<BB * SS / 32, 256>>>(t, r, Wsc, bsc, logd);
    k_softmax_gather<<<BB, 256>>>(t, r, bto, bro, logd, pose);
    dim3 gh(64, 2, 4);
    k_hidden<<<gh, 256>>>(Wth, bth, Wto, Wrh, brh, Wro, pose);
}

// round 10
// speedup vs baseline: 1.2803x; 1.2803x over previous
#include <cuda_runtime.h>
#include <math.h>

#define BB 1024
#define SS 64
#define DD 256
#define CHN 1024
#define NCH 8    // samples per chunk (k_hidden)

typedef unsigned long long u64;

// scratch (device globals; no allocation allowed)
__device__ int   g_idx[BB];
__device__ int   g_cnt[SS];               // per-scene sample counts
__device__ int   g_list[SS][BB];          // per-scene sample lists (global ordering)
__device__ __align__(16) float g_desc[2][BB][DD];   // gathered descriptors (t, rot)

// ---- packed f32x2 helpers (Blackwell) --------------------------------------
__device__ __forceinline__ u64 dup2(float w) {
    unsigned u = __float_as_uint(w);
    u64 r; asm("mov.b64 %0, {%1, %2};" : "=l"(r) : "r"(u), "r"(u)); return r;
}
__device__ __forceinline__ float2 unpk2(u64 v) {
    unsigned lo, hi; asm("mov.b64 {%0, %1}, %2;" : "=r"(lo), "=r"(hi) : "l"(v));
    return make_float2(__uint_as_float(lo), __uint_as_float(hi));
}
__device__ __forceinline__ u64 ffma2(u64 a, u64 b, u64 c) {
    u64 d; asm("fma.rn.f32x2 %0, %1, %2, %3;" : "=l"(d) : "l"(a), "l"(b), "l"(c));
    return d;
}

// ---------------------------------------------------------------------------
// K1: logits for 2 rows per warp (8 LDG.128 in flight, W regs shared).
// Block 0 also zeroes g_cnt (safe: consumers are in later kernels).
// ---------------------------------------------------------------------------
__global__ void __launch_bounds__(256) k_logits(
        const float* __restrict__ t, const float* __restrict__ r,
        const float* __restrict__ Wsc, const float* __restrict__ bsc,
        float* __restrict__ logits) {
    if (blockIdx.x == 0 && threadIdx.x < SS) g_cnt[threadIdx.x] = 0;
    int g    = blockIdx.x * 8 + (threadIdx.x >> 5);   // warp id
    int lane = threadIdx.x & 31;
    int w0   = g * 2;
    if (w0 >= BB * SS) return;
    const float4* t40 = (const float4*)(t + (size_t)w0 * DD);
    const float4* r40 = (const float4*)(r + (size_t)w0 * DD);
    const float4* t41 = t40 + DD / 4;
    const float4* r41 = r40 + DD / 4;
    const float4* W4  = (const float4*)Wsc;
    float acc0 = 0.f, acc1 = 0.f;
#pragma unroll
    for (int j = 0; j < 2; j++) {
        int k = j * 32 + lane;
        float4 wa = W4[k];
        float4 wb = W4[64 + k];
        float4 a0 = t40[k], b0 = r40[k];
        float4 a1 = t41[k], b1 = r41[k];
        acc0 = fmaf(a0.x, wa.x, acc0); acc0 = fmaf(a0.y, wa.y, acc0);
        acc0 = fmaf(a0.z, wa.z, acc0); acc0 = fmaf(a0.w, wa.w, acc0);
        acc0 = fmaf(b0.x, wb.x, acc0); acc0 = fmaf(b0.y, wb.y, acc0);
        acc0 = fmaf(b0.z, wb.z, acc0); acc0 = fmaf(b0.w, wb.w, acc0);
        acc1 = fmaf(a1.x, wa.x, acc1); acc1 = fmaf(a1.y, wa.y, acc1);
        acc1 = fmaf(a1.z, wa.z, acc1); acc1 = fmaf(a1.w, wa.w, acc1);
        acc1 = fmaf(b1.x, wb.x, acc1); acc1 = fmaf(b1.y, wb.y, acc1);
        acc1 = fmaf(b1.z, wb.z, acc1); acc1 = fmaf(b1.w, wb.w, acc1);
    }
#pragma unroll
    for (int o = 16; o; o >>= 1) {
        acc0 += __shfl_xor_sync(0xFFFFFFFFu, acc0, o);
        acc1 += __shfl_xor_sync(0xFFFFFFFFu, acc1, o);
    }
    if (lane == 0) {
        float bb = bsc[0];
        logits[w0]     = acc0 + bb;
        logits[w0 + 1] = acc1 + bb;
    }
}

// ---------------------------------------------------------------------------
// K2: log_softmax + argmax (warp-parallel) + scene-list append + gather + bias
// ---------------------------------------------------------------------------
__global__ void k_softmax_gather(const float* __restrict__ t, const float* __restrict__ r,
                                 const float* __restrict__ bto, const float* __restrict__ bro,
                                 float* __restrict__ logd, float* __restrict__ pose) {
    int b    = blockIdx.x;
    int tid  = threadIdx.x;
    int wid  = tid >> 5;
    int lane = tid & 31;
    __shared__ float l[SS];
    __shared__ float lse;
    __shared__ int   am;
    if (tid < SS) l[tid] = logd[b * SS + tid];
    __syncthreads();
    if (wid == 0) {
        float v0 = l[lane], v1 = l[lane + 32];
        float m; int a;
        if (v1 > v0) { m = v1; a = lane + 32; } else { m = v0; a = lane; }
#pragma unroll
        for (int o = 16; o; o >>= 1) {
            float mo = __shfl_down_sync(0xFFFFFFFFu, m, o);
            int   ao = __shfl_down_sync(0xFFFFFFFFu, a, o);
            if (mo > m || (mo == m && ao < a)) { m = mo; a = ao; }
        }
        m = __shfl_sync(0xFFFFFFFFu, m, 0);
        a = __shfl_sync(0xFFFFFFFFu, a, 0);
        float s = expf(v0 - m) + expf(v1 - m);
#pragma unroll
        for (int o = 16; o; o >>= 1) s += __shfl_xor_sync(0xFFFFFFFFu, s, o);
        if (lane == 0) {
            lse = m + logf(s);
            am  = a;
            g_idx[b] = a;
            int p = atomicAdd(&g_cnt[a], 1);   // single global ordering
            g_list[a][p] = b;
        }
    }
    __syncthreads();
    if (tid < SS) logd[b * SS + tid] = l[tid] - lse;
    int a = am;
    if (tid >= 224) {                          // pose bias init
        int o = tid - 224;
        if (o < 3)      pose[b * 7 + o] = bto[a * 3 + o];
        else if (o < 7) pose[b * 7 + o] = bro[a * 4 + (o - 3)];
    }
    if (tid < 64) {
        ((float4*)g_desc[0][b])[tid] =
            ((const float4*)(t + ((size_t)b * SS + a) * DD))[tid];
    } else if (tid < 128) {
        int i = tid - 64;
        ((float4*)g_desc[1][b])[i] =
            ((const float4*)(r + ((size_t)b * SS + a) * DD))[i];
    }
}

// ---------------------------------------------------------------------------
// K3: fused expert hidden layer + gelu + output projection.
// grid = (64 scenes, 2 heads, 4 jc chunk-slots), 256 threads.
// Thread owns 4 CONSECUTIVE channels (float4 weight LDG.128) x 8 samples
// (4 f32x2 pairs per channel) -> 16 u64 accumulators.
// ---------------------------------------------------------------------------
__global__ void __launch_bounds__(256, 3) k_hidden(
        const float* __restrict__ Wth, const float* __restrict__ bth,
        const float* __restrict__ Wto,
        const float* __restrict__ Wrh, const float* __restrict__ brh,
        const float* __restrict__ Wro,
        float* __restrict__ pose) {
    int scene = blockIdx.x;            // 0..63
    int head  = blockIdx.y;            // 0..1
    int jc    = blockIdx.z;            // chunk slot 0..3
    int tid   = threadIdx.x;
    int lane  = tid & 31;

    int cnt = g_cnt[scene];
    if (jc * NCH >= cnt) return;
    const int* list = g_list[scene];

    const float* W    = head ? Wrh : Wth;
    const float* bias = head ? brh : bth;
    const float* Wo   = head ? Wro : Wto;
    const int    NO   = head ? 4 : 3;
    const int    ooff = head ? 3 : 0;

    __shared__ __align__(16) float gs[DD][NCH + 2];   // transposed, padded
    __shared__ float part[NCH][4];

    int ch = tid * 4;                                  // 4 consecutive channels
    const float* Ws = W + (size_t)scene * DD * CHN;

    for (int c0 = jc * NCH; c0 < cnt; c0 += 4 * NCH) {
        int nc = min(NCH, cnt - c0);
        __syncthreads();    // protect gs/part reuse across chunks
        {
            const float* gd = &g_desc[head][0][0];
#pragma unroll
            for (int n = 0; n < NCH; n++) {
                float v = (n < nc) ? gd[(size_t)list[c0 + n] * DD + tid] : 0.f;
                gs[tid][n] = v;
            }
        }
        if (tid < NCH * 4) part[tid >> 2][tid & 3] = 0.f;
        __syncthreads();

        u64 acc[4][4];      // [channel][sample-pair]
#pragma unroll
        for (int c = 0; c < 4; c++)
#pragma unroll
            for (int p = 0; p < 4; p++) acc[c][p] = 0ull;

#pragma unroll 4
        for (int d = 0; d < DD; d++) {
            float4 wv = *(const float4*)&Ws[(size_t)d * CHN + ch];
            u64 wd[4] = {dup2(wv.x), dup2(wv.y), dup2(wv.z), dup2(wv.w)};
            const u64* grow = (const u64*)&gs[d][0];
#pragma unroll
            for (int p = 0; p < 4; p++) {
                u64 gp = grow[p];
#pragma unroll
                for (int c = 0; c < 4; c++)
                    acc[c][p] = ffma2(gp, wd[c], acc[c][p]);
            }
        }

        // epilogue (loads here to keep main-loop register pressure low)
        float4 bv = *(const float4*)&bias[(size_t)scene * CHN + ch];
        float bvs[4] = {bv.x, bv.y, bv.z, bv.w};
        float wo[4][4];
#pragma unroll
        for (int c = 0; c < 4; c++)
#pragma unroll
            for (int o = 0; o < 4; o++)
                wo[c][o] = (o < NO) ? Wo[((size_t)scene * CHN + ch + c) * NO + o] : 0.f;

#pragma unroll
        for (int p = 0; p < 4; p++) {
            float2 xs[4];
#pragma unroll
            for (int c = 0; c < 4; c++) xs[c] = unpk2(acc[c][p]);
#pragma unroll
            for (int q = 0; q < 2; q++) {
                int n = 2 * p + q;
                if (n < nc) {                       // warp-uniform
                    float pv[4] = {0.f, 0.f, 0.f, 0.f};
#pragma unroll
                    for (int c = 0; c < 4; c++) {
                        float x = (q ? xs[c].y : xs[c].x) + bvs[c];
                        float h = 0.5f * x * (1.0f + erff(x * 0.70710678118654752f));
#pragma unroll
                        for (int o = 0; o < 4; o++) pv[o] = fmaf(h, wo[c][o], pv[o]);
                    }
#pragma unroll
                    for (int off = 16; off; off >>= 1) {
                        pv[0] += __shfl_down_sync(0xFFFFFFFFu, pv[0], off);
                        pv[1] += __shfl_down_sync(0xFFFFFFFFu, pv[1], off);
                        pv[2] += __shfl_down_sync(0xFFFFFFFFu, pv[2], off);
                        pv[3] += __shfl_down_sync(0xFFFFFFFFu, pv[3], off);
                    }
                    if (lane == 0) {
                        atomicAdd(&part[n][0], pv[0]);
                        atomicAdd(&part[n][1], pv[1]);
                        atomicAdd(&part[n][2], pv[2]);
                        atomicAdd(&part[n][3], pv[3]);
                    }
                }
            }
        }
        __syncthreads();
        if (tid < NCH * 4) {
            int n = tid >> 2, o = tid & 3;
            if (n < nc && o < NO)
                atomicAdd(&pose[(size_t)list[c0 + n] * 7 + ooff + o], part[n][o]);
        }
    }
}

// ---------------------------------------------------------------------------
extern "C" void kernel_launch(void* const* d_in, const int* in_sizes, int n_in,
                              void* d_out, int out_size) {
    const float* t   = (const float*)d_in[0];
    const float* r   = (const float*)d_in[1];
    const float* Wsc = (const float*)d_in[2];
    const float* bsc = (const float*)d_in[3];
    const float* Wth = (const float*)d_in[4];
    const float* bth = (const float*)d_in[5];
    const float* Wto = (const float*)d_in[6];
    const float* bto = (const float*)d_in[7];
    const float* Wrh = (const float*)d_in[8];
    const float* brh = (const float*)d_in[9];
    const float* Wro = (const float*)d_in[10];
    const float* bro = (const float*)d_in[11];

    float* out  = (float*)d_out;
    float* pose = out;             // [B,7]
    float* logd = out + BB * 7;    // [B,S]

    k_logits<<<BB * SS / 16, 256>>>(t, r, Wsc, bsc, logd);
    k_softmax_gather<<<BB, 256>>>(t, r, bto, bro, logd, pose);
    dim3 gh(64, 2, 4);
    k_hidden<<<gh, 256>>>(Wth, bth, Wto, Wrh, brh, Wro, pose);
}